// round 8
// baseline (speedup 1.0000x reference)
#include <cuda_runtime.h>
#include <cstdint>

#define THREADS  256
#define P_BLK    2
#define NBLOCKS  512                 // 1024 patches / 2

// x tile: 16 KB staged as 16B granules, granule(c,pp,b) at idx c*33 + pp*16 + b
#define CSTRIDE4 33
// smem also reused as 32 KB reduction buffer after __syncthreads
#define SMEM_BYTES 32768

typedef unsigned long long ull;

__global__ __launch_bounds__(THREADS, 2)
void lc1d_v6(const float* __restrict__ x,
             const float* __restrict__ w,
             float* __restrict__ out)
{
    __shared__ __align__(16) char sm[SMEM_BYTES];

    const int tid = threadIdx.x;
    const int blk = blockIdx.x;

    // ---------------- producer: stage x tile ----------------
    {
        const float4* x4 = reinterpret_cast<const float4*>(x);
        float4* xs4 = reinterpret_cast<float4*>(sm);
        #pragma unroll
        for (int it = 0; it < 4; ++it) {
            int i  = it * THREADS + tid;     // 0..1023
            int pp = i & 1;
            int b  = (i >> 1) & 15;
            int c  = i >> 5;                 // 0..31
            float4 v = x4[(size_t)(b * 32 + c) * 1024 + blk * P_BLK + pp];
            xs4[c * CSTRIDE4 + pp * 16 + b] = v;
        }
    }
    __syncthreads();

    // ---------------- consumer ----------------
    const int lane = tid & 31;
    const int wid  = tid >> 5;
    const int pp   = lane & 1;
    const int og   = lane >> 1;          // o = 4*og + i
    const int cs   = wid & 3;            // c in [8cs, 8cs+8)
    const int bq   = wid >> 2;           // b in [8bq, 8bq+8)
    const int p    = blk * P_BLK + pp;

    uint32_t sbase;
    asm("{ .reg .u64 t; cvta.to.shared.u64 t, %1; cvt.u32.u64 %0, t; }"
        : "=r"(sbase) : "l"(sm));
    const uint32_t xbase = sbase + 16u * (uint32_t)(8 * cs * CSTRIDE4 + pp * 16 + 8 * bq);

    // acc[i*8+q]: o = 4og+i, b = 8bq+q; f32x2 lanes hold (k0+k2, k1+k3) partials
    ull acc[32];
    #pragma unroll
    for (int t = 0; t < 32; ++t) acc[t] = 0ULL;

    // w 16B granules: idx = (o*32 + c)*1024 + p
    const ulonglong2* wp = reinterpret_cast<const ulonglong2*>(w)
                         + (size_t)(4 * og) * 32768 + (size_t)(8 * cs) * 1024
                         + blk * P_BLK + pp;

    ull wlo[2][4], whi[2][4];
    #pragma unroll
    for (int i = 0; i < 4; ++i) {
        ulonglong2 t = wp[(size_t)i * 32768];
        wlo[0][i] = t.x; whi[0][i] = t.y;
    }

    #pragma unroll
    for (int j = 0; j < 8; ++j) {        // 8 input channels per warp
        const int cur = j & 1, nxt = cur ^ 1;
        if (j < 7) {
            const ulonglong2* wn = wp + (size_t)(j + 1) * 1024;
            #pragma unroll
            for (int i = 0; i < 4; ++i) {
                ulonglong2 t = wn[(size_t)i * 32768];
                wlo[nxt][i] = t.x; whi[nxt][i] = t.y;
            }
        }
        const uint32_t xa = xbase + (uint32_t)(j * CSTRIDE4 * 16);
        #pragma unroll
        for (int q = 0; q < 8; ++q) {
            ull xlo, xhi;
            asm("ld.shared.v2.u64 {%0, %1}, [%2];"
                : "=l"(xlo), "=l"(xhi) : "r"(xa + 16u * q));
            #pragma unroll
            for (int i = 0; i < 4; ++i) {
                asm("fma.rn.f32x2 %0, %1, %2, %0;"
                    : "+l"(acc[i * 8 + q]) : "l"(xlo), "l"(wlo[cur][i]));
                asm("fma.rn.f32x2 %0, %1, %2, %0;"
                    : "+l"(acc[i * 8 + q]) : "l"(xhi), "l"(whi[cur][i]));
            }
        }
    }

    // ---------------- cross-warp (cs) reduction in smem ----------------
    __syncthreads();                      // x tile no longer needed
    ull* rb = reinterpret_cast<ull*>(sm);

    // round 1: cs odd -> store; cs even partner adds.  layout [t][r(4)][lane]
    if (cs & 1) {
        ull* d = rb + (size_t)((bq * 2 + (cs >> 1)) * 32 + lane);
        #pragma unroll
        for (int t = 0; t < 32; ++t) d[t * 128] = acc[t];
    }
    __syncthreads();
    if (!(cs & 1)) {
        const ull* s = rb + (size_t)((bq * 2 + (cs >> 1)) * 32 + lane);
        #pragma unroll
        for (int t = 0; t < 32; ++t) {
            ull v = s[t * 128];
            asm("add.rn.f32x2 %0, %0, %1;" : "+l"(acc[t]) : "l"(v));
        }
    }
    __syncthreads();
    // round 2: cs==2 -> store; cs==0 adds and writes out.  layout [t][r(2)][lane]
    if (cs == 2) {
        ull* d = rb + (size_t)(bq * 32 + lane);
        #pragma unroll
        for (int t = 0; t < 32; ++t) d[t * 64] = acc[t];
    }
    __syncthreads();
    if (cs == 0) {
        const ull* s = rb + (size_t)(bq * 32 + lane);
        #pragma unroll
        for (int t = 0; t < 32; ++t) {
            ull v = s[t * 64];
            asm("add.rn.f32x2 %0, %0, %1;" : "+l"(acc[t]) : "l"(v));
        }
        const float sc = 0.17677669529663687f;   // 1/sqrt(32)
        #pragma unroll
        for (int i = 0; i < 4; ++i) {
            const int o = 4 * og + i;
            #pragma unroll
            for (int q = 0; q < 8; ++q) {
                float lo, hi;
                asm("mov.b64 {%0, %1}, %2;" : "=f"(lo), "=f"(hi) : "l"(acc[i * 8 + q]));
                const int b = 8 * bq + q;
                out[(size_t)b * 65536 + (size_t)o * 1024 + p] = (lo + hi) * sc;
            }
        }
    }
}

extern "C" void kernel_launch(void* const* d_in, const int* in_sizes, int n_in,
                              void* d_out, int out_size)
{
    const float* x = (const float*)d_in[0];   // [16, 32, 4096]
    const float* w = (const float*)d_in[1];   // [64, 32, 4096]
    float* out = (float*)d_out;               // [16, 64, 1024]
    (void)in_sizes; (void)n_in; (void)out_size;

    lc1d_v6<<<NBLOCKS, THREADS>>>(x, w, out);
}

// round 11
// speedup vs baseline: 1.4730x; 1.4730x over previous
#include <cuda_runtime.h>
#include <cstdint>

#define THREADS 128
#define NBLOCKS 256     // 128 patch-blocks (8 patches each) x 2 o-halves

typedef unsigned long long ull;

// smem x tile (one c-pass): 16c x 4k x 4q x 8pp granules of 16B = 32 KB
// granule (c,k,q,pp) = 4 floats = batches {4q..4q+3} at (c, patch pp, k)
#define GR(c,k,q,pp) ((((c)*4+(k))*4+(q))*8+(pp))

__global__ __launch_bounds__(THREADS, 2)
void lc1d_v8(const float* __restrict__ x,
             const float* __restrict__ w,
             float* __restrict__ out)
{
    __shared__ __align__(16) float4 xs[2048];   // 32 KB

    const int tid   = threadIdx.x;
    const int pb    = blockIdx.x >> 1;          // patch-block: patches 8pb..8pb+7
    const int obase = (blockIdx.x & 1) * 32;    // o half

    const int lane = tid & 31;
    const int pp   = lane & 7;                  // patch within block (fast lane dim)
    const int ogl  = lane >> 3;                 // 0..3
    const int wrp  = tid >> 5;
    const int ogh  = wrp & 1;
    const int bq   = wrp >> 1;                  // batches 8bq .. 8bq+7
    const int og   = ogh * 4 + ogl;             // 0..7 ; o = obase + 4og + i

    const float4* x4 = reinterpret_cast<const float4*>(x);
    const float4* w4 = reinterpret_cast<const float4*>(w);
    const ulonglong2* xsu = reinterpret_cast<const ulonglong2*>(xs);

    // acc[i*4+bp]: o = obase+4og+i, batches (8bq+2bp, 8bq+2bp+1) in f32x2 lanes
    ull acc[16];
    #pragma unroll
    for (int t = 0; t < 16; ++t) acc[t] = 0ULL;

    // w granule (16B, k-quad): idx = (o*32 + c)*1024 + pb*8 + pp
    const size_t wb = (size_t)(obase + 4 * og) * 32 * 1024 + (size_t)pb * 8 + pp;

    #pragma unroll
    for (int pass = 0; pass < 2; ++pass) {
        const int c0 = pass * 16;
        if (pass) __syncthreads();              // previous compute done reading xs

        // ---- producer: stage 16 c's, transposing k-quads -> b-quads ----
        #pragma unroll
        for (int it = 0; it < 4; ++it) {
            int gi = it * THREADS + tid;        // 0..511 transpose groups
            int g  = gi & 3;                    // b-quad
            int pq = (gi >> 2) & 7;             // patch lane
            int c  = gi >> 5;                   // 0..15
            float4 v0 = x4[(size_t)((4 * g + 0) * 32 + c0 + c) * 1024 + pb * 8 + pq];
            float4 v1 = x4[(size_t)((4 * g + 1) * 32 + c0 + c) * 1024 + pb * 8 + pq];
            float4 v2 = x4[(size_t)((4 * g + 2) * 32 + c0 + c) * 1024 + pb * 8 + pq];
            float4 v3 = x4[(size_t)((4 * g + 3) * 32 + c0 + c) * 1024 + pb * 8 + pq];
            xs[GR(c, 0, g, pq)] = make_float4(v0.x, v1.x, v2.x, v3.x);
            xs[GR(c, 1, g, pq)] = make_float4(v0.y, v1.y, v2.y, v3.y);
            xs[GR(c, 2, g, pq)] = make_float4(v0.z, v1.z, v2.z, v3.z);
            xs[GR(c, 3, g, pq)] = make_float4(v0.w, v1.w, v2.w, v3.w);
        }
        __syncthreads();

        // ---- consumer: 16 c's, w double-buffered in registers ----
        float4 wv[2][4];
        #pragma unroll
        for (int i = 0; i < 4; ++i)
            wv[0][i] = w4[wb + (size_t)(i * 32 + c0) * 1024];

        #pragma unroll
        for (int c = 0; c < 16; ++c) {
            const int cur = c & 1, nxt = cur ^ 1;
            if (c + 1 < 16) {
                #pragma unroll
                for (int i = 0; i < 4; ++i)
                    wv[nxt][i] = w4[wb + (size_t)(i * 32 + c0 + c + 1) * 1024];
            }

            #pragma unroll
            for (int k = 0; k < 4; ++k) {
                // two b-quads (q = 2bq, 2bq+1): typed C++ loads (ordered vs barriers)
                ulonglong2 g0 = xsu[GR(c, k, 2 * bq, pp)];
                ulonglong2 g1 = xsu[GR(c, k, 2 * bq + 1, pp)];
                const ull xp0 = g0.x, xp1 = g0.y, xp2 = g1.x, xp3 = g1.y;

                #pragma unroll
                for (int i = 0; i < 4; ++i) {
                    float wk = (k == 0) ? wv[cur][i].x : (k == 1) ? wv[cur][i].y
                             : (k == 2) ? wv[cur][i].z : wv[cur][i].w;
                    ull wd;
                    asm("mov.b64 %0, {%1, %1};" : "=l"(wd) : "f"(wk));
                    asm("fma.rn.f32x2 %0, %1, %2, %0;" : "+l"(acc[i * 4 + 0]) : "l"(xp0), "l"(wd));
                    asm("fma.rn.f32x2 %0, %1, %2, %0;" : "+l"(acc[i * 4 + 1]) : "l"(xp1), "l"(wd));
                    asm("fma.rn.f32x2 %0, %1, %2, %0;" : "+l"(acc[i * 4 + 2]) : "l"(xp2), "l"(wd));
                    asm("fma.rn.f32x2 %0, %1, %2, %0;" : "+l"(acc[i * 4 + 3]) : "l"(xp3), "l"(wd));
                }
            }
        }
    }

    // ---------------- epilogue: scale and store ----------------
    const float sc = 0.17677669529663687f;   // 1/sqrt(32)
    const int p = pb * 8 + pp;
    #pragma unroll
    for (int i = 0; i < 4; ++i) {
        const int o = obase + 4 * og + i;
        #pragma unroll
        for (int bp = 0; bp < 4; ++bp) {
            float lo, hi;
            asm("mov.b64 {%0, %1}, %2;" : "=f"(lo), "=f"(hi) : "l"(acc[i * 4 + bp]));
            const int b = 8 * bq + 2 * bp;
            out[(size_t)b * 65536 + (size_t)o * 1024 + p]       = lo * sc;
            out[(size_t)(b + 1) * 65536 + (size_t)o * 1024 + p] = hi * sc;
        }
    }
}

extern "C" void kernel_launch(void* const* d_in, const int* in_sizes, int n_in,
                              void* d_out, int out_size)
{
    const float* x = (const float*)d_in[0];   // [16, 32, 4096]
    const float* w = (const float*)d_in[1];   // [64, 32, 4096]
    float* out = (float*)d_out;               // [16, 64, 1024]
    (void)in_sizes; (void)n_in; (void)out_size;

    lc1d_v8<<<NBLOCKS, THREADS>>>(x, w, out);
}